// round 3
// baseline (speedup 1.0000x reference)
#include <cuda_runtime.h>
#include <cuda_bf16.h>

#define NN 100000
#define EE 1000000
#define HID 64
#define NCHUNK 1024
#define NBLK 98            // ceil(NN / NCHUNK)
#define BN_EPS 1e-5f

// ---------------- scratch ----------------------------------------------------
__device__ __align__(16) int   g_deg[NN];
__device__ __align__(16) float g_dinv[NN];
__device__ __align__(16) int   g_rowptr[NN + 1];
__device__ __align__(16) int   g_cursor[NN];
__device__ __align__(16) int   g_src[EE + NN];
__device__ __align__(16) float g_h[NN * HID];
__device__ __align__(16) float g_x1[NN * HID];
__device__ __align__(16) float g_x2[NN * HID];
__device__ __align__(16) int   g_bsum[128];

// packed f32x2 helpers (FFMA2 — only reachable via PTX)
#define FFMA2(acc, a, b) \
    asm("fma.rn.f32x2 %0, %1, %2, %0;" : "+l"(acc) : "l"(a), "l"(b))
#define PACK_DUP(dst, x) \
    asm("mov.b64 %0, {%1, %1};" : "=l"(dst) : "f"(x))
#define UNPACK2(lo, hi, v) \
    asm("mov.b64 {%0, %1}, %2;" : "=f"(lo), "=f"(hi) : "l"(v))

// ---------------- preprocessing ---------------------------------------------

__global__ void init_deg_kernel() {
    int i = blockIdx.x * blockDim.x + threadIdx.x;
    if (i < NN) g_deg[i] = 1;          // self loop
    if (i == 0) g_rowptr[NN] = EE + NN;
}

__global__ void count_kernel(const int* __restrict__ col) {
    int i = blockIdx.x * blockDim.x + threadIdx.x;
    if (i < EE) {
        unsigned c = (unsigned)col[i];
        if (c < NN) atomicAdd(&g_deg[c], 1);
    }
}

// per-1024-chunk degree sums + dinv
__global__ void partials_kernel() {
    int tid = threadIdx.x, b = blockIdx.x;
    int base = b * NCHUNK + tid * 4;
    int s = 0;
#pragma unroll
    for (int j = 0; j < 4; j++) {
        int idx = base + j;
        if (idx < NN) {
            int d = g_deg[idx];
            s += d;
            g_dinv[idx] = rsqrtf((float)d);
        }
    }
    for (int d = 16; d; d >>= 1) s += __shfl_down_sync(0xffffffffu, s, d);
    __shared__ int wsum[8];
    int lane = tid & 31, wid = tid >> 5;
    if (lane == 0) wsum[wid] = s;
    __syncthreads();
    if (tid == 0) {
        int t = 0;
#pragma unroll
        for (int i = 0; i < 8; i++) t += wsum[i];
        g_bsum[b] = t;
    }
}

// each block computes its own chunk offset (prefix over <=98 chunk sums),
// then scans its 1024 degrees into rowptr/cursor. (scan_top eliminated)
__global__ void scan_chunks_kernel() {
    int b = blockIdx.x, tid = threadIdx.x;
    int lane = tid & 31, wid = tid >> 5;

    // block-wide sum of g_bsum[t] for t < b
    int p = (tid < b && tid < NBLK) ? g_bsum[tid] : 0;   // blockDim 256 >= NBLK
    for (int d = 16; d; d >>= 1) p += __shfl_down_sync(0xffffffffu, p, d);
    __shared__ int psum[8];
    if (lane == 0) psum[wid] = p;
    __syncthreads();
    __shared__ int chunk_off;
    if (tid == 0) {
        int t = 0;
#pragma unroll
        for (int i = 0; i < 8; i++) t += psum[i];
        chunk_off = t;
    }

    int base = b * NCHUNK + tid * 4;
    int v[4]; int s = 0;
#pragma unroll
    for (int j = 0; j < 4; j++) {
        int idx = base + j;
        v[j] = (idx < NN) ? g_deg[idx] : 0;
        s += v[j];
    }
    int x = s;
#pragma unroll
    for (int d = 1; d < 32; d <<= 1) {
        int y = __shfl_up_sync(0xffffffffu, x, d);
        if (lane >= d) x += y;
    }
    __shared__ int wsum[8], woff[8];
    if (lane == 31) wsum[wid] = x;
    __syncthreads();
    if (tid == 0) {
        int run = 0;
#pragma unroll
        for (int i = 0; i < 8; i++) { int t = wsum[i]; woff[i] = run; run += t; }
    }
    __syncthreads();
    int pos = chunk_off + woff[wid] + (x - s);
#pragma unroll
    for (int j = 0; j < 4; j++) {
        int idx = base + j;
        if (idx < NN) {
            g_rowptr[idx] = pos;
            g_cursor[idx] = pos;
            pos += v[j];
        }
    }
}

__global__ void bin_kernel(const int* __restrict__ ei) {
    int i = blockIdx.x * blockDim.x + threadIdx.x;
    if (i >= EE + NN) return;
    unsigned s, c;
    if (i < EE) { s = (unsigned)ei[i]; c = (unsigned)ei[EE + i]; }
    else        { s = c = (unsigned)(i - EE); }
    if (s >= NN || c >= NN) return;
    int p = atomicAdd(&g_cursor[c], 1);
    if ((unsigned)p < (unsigned)(EE + NN)) g_src[p] = (int)s;
}

// ---------------- GEMM: h[n,:] = dinv[n] * (X[n,:] @ W) ----------------------
// 64 nodes/block, 128 threads, thread tile = 4 nodes x 8 cols, FFMA2 math.
// xs staged k-major (xs[k*64+n]) -> conflict-free LDS.32 broadcasts.
template <int K>
__global__ void __launch_bounds__(128) gemm_kernel(const float* __restrict__ Xext,
                                                   const float* __restrict__ W,
                                                   int layer) {
    __shared__ __align__(16) float xs[K * 64];
    __shared__ __align__(16) float ws[K * HID];
    const float* X = Xext ? Xext : (layer == 1 ? (const float*)g_x1 : (const float*)g_x2);

    const int tid  = threadIdx.x;
    const int base = blockIdx.x * 64;

    // stage W [K, 64] (vectorized; K*HID % 4 == 0 for K=37 and 64)
    for (int i = tid; i < K * HID / 4; i += 128)
        ((float4*)ws)[i] = ((const float4*)W)[i];

    // stage X transposed: xs[k*64 + n] = X[base+n][k]
    if constexpr ((K & 3) == 0) {
        for (int i = tid; i < 64 * (K / 4); i += 128) {
            int n  = i / (K / 4);
            int k4 = (i % (K / 4)) * 4;
            float4 v = make_float4(0.f, 0.f, 0.f, 0.f);
            if (base + n < NN) v = *(const float4*)&X[(size_t)(base + n) * K + k4];
            xs[(k4 + 0) * 64 + n] = v.x;
            xs[(k4 + 1) * 64 + n] = v.y;
            xs[(k4 + 2) * 64 + n] = v.z;
            xs[(k4 + 3) * 64 + n] = v.w;
        }
    } else {
        for (int i = tid; i < 64 * K; i += 128) {
            int n = i / K, k = i % K;
            xs[k * 64 + n] = (base + n < NN) ? X[(size_t)(base + n) * K + k] : 0.0f;
        }
    }
    __syncthreads();

    const int cg = tid & 7;    // 8 col groups x 8 cols
    const int ng = tid >> 3;   // 16 node groups x 4 nodes
    unsigned long long acc[4][4];
#pragma unroll
    for (int j = 0; j < 4; j++)
#pragma unroll
        for (int q = 0; q < 4; q++) acc[j][q] = 0ull;

    const float* wrow = &ws[cg * 8];
    const float* xcol = &xs[ng * 4];

#pragma unroll 8
    for (int k = 0; k < K; k++) {
        ulonglong2 wA = *(const ulonglong2*)(wrow + k * HID);       // cols 0-3 (2 pairs)
        ulonglong2 wB = *(const ulonglong2*)(wrow + k * HID + 4);   // cols 4-7
#pragma unroll
        for (int j = 0; j < 4; j++) {
            float xv = xcol[k * 64 + j];
            unsigned long long xd;
            PACK_DUP(xd, xv);
            FFMA2(acc[j][0], xd, wA.x);
            FFMA2(acc[j][1], xd, wA.y);
            FFMA2(acc[j][2], xd, wB.x);
            FFMA2(acc[j][3], xd, wB.y);
        }
    }

#pragma unroll
    for (int j = 0; j < 4; j++) {
        int n = base + ng * 4 + j;
        if (n < NN) {
            float di = g_dinv[n];
            float o[8];
#pragma unroll
            for (int q = 0; q < 4; q++) UNPACK2(o[2 * q], o[2 * q + 1], acc[j][q]);
            float4 v0 = make_float4(di * o[0], di * o[1], di * o[2], di * o[3]);
            float4 v1 = make_float4(di * o[4], di * o[5], di * o[6], di * o[7]);
            *(float4*)&g_h[n * HID + cg * 8]     = v0;
            *(float4*)&g_h[n * HID + cg * 8 + 4] = v1;
        }
    }
}

// ---------------- SpMM (gather, CSR) + fused BN/ReLU/residual epilogue -------
// one warp per node, 2 cols per lane (float2), unroll-4 MLP
__global__ void spmm_epi_kernel(int layer,
                                const float* __restrict__ bias,
                                const float* __restrict__ gamma,
                                const float* __restrict__ beta,
                                const float* __restrict__ mean,
                                const float* __restrict__ var,
                                float* __restrict__ out_final) {
    int gw = (blockIdx.x * blockDim.x + threadIdx.x) >> 5;
    if (gw >= NN) return;
    int lane = threadIdx.x & 31;
    int c = lane * 2;

    const float* __restrict__ H = g_h;
    const float* resid = (layer == 0) ? nullptr
                        : (layer == 1 ? (const float*)g_x1 : (const float*)g_x2);
    float* out = (layer == 0) ? g_x1 : (layer == 1 ? g_x2 : out_final);

    int beg = g_rowptr[gw];
    int end = g_rowptr[gw + 1];

    float2 a0 = make_float2(0.f, 0.f), a1 = make_float2(0.f, 0.f);
    float2 a2 = make_float2(0.f, 0.f), a3 = make_float2(0.f, 0.f);
    int e = beg;
    for (; e + 3 < end; e += 4) {
        int s0 = g_src[e],     s1 = g_src[e + 1];
        int s2 = g_src[e + 2], s3 = g_src[e + 3];
        float2 v0 = *(const float2*)(H + s0 * HID + c);
        float2 v1 = *(const float2*)(H + s1 * HID + c);
        float2 v2 = *(const float2*)(H + s2 * HID + c);
        float2 v3 = *(const float2*)(H + s3 * HID + c);
        a0.x += v0.x; a0.y += v0.y;
        a1.x += v1.x; a1.y += v1.y;
        a2.x += v2.x; a2.y += v2.y;
        a3.x += v3.x; a3.y += v3.y;
    }
    for (; e < end; e++) {
        int s = g_src[e];
        float2 v = *(const float2*)(H + s * HID + c);
        a0.x += v.x; a0.y += v.y;
    }

    float sx = (a0.x + a1.x) + (a2.x + a3.x);
    float sy = (a0.y + a1.y) + (a2.y + a3.y);

    float di = g_dinv[gw];
    float scx = gamma[c]     * rsqrtf(var[c]     + BN_EPS);
    float scy = gamma[c + 1] * rsqrtf(var[c + 1] + BN_EPS);
    float vx = (sx * di + bias[c]     - mean[c])     * scx + beta[c];
    float vy = (sy * di + bias[c + 1] - mean[c + 1]) * scy + beta[c + 1];
    vx = fmaxf(vx, 0.0f);
    vy = fmaxf(vy, 0.0f);
    if (resid) {
        float2 r = *(const float2*)(resid + gw * HID + c);
        vx += r.x; vy += r.y;
    }
    *(float2*)(out + gw * HID + c) = make_float2(vx, vy);
}

// ---------------- launch -----------------------------------------------------
extern "C" void kernel_launch(void* const* d_in, const int* in_sizes, int n_in,
                              void* d_out, int out_size) {
    const float* x   = (const float*)d_in[0];
    const int*   ei  = (const int*)d_in[1];     // int32 (JAX default, no x64)
    const float* W1  = (const float*)d_in[2];
    const float* W2  = (const float*)d_in[3];
    const float* W3  = (const float*)d_in[4];
    const float* b   = (const float*)d_in[5];
    const float* gma = (const float*)d_in[6];
    const float* bta = (const float*)d_in[7];
    const float* mu  = (const float*)d_in[8];
    const float* var = (const float*)d_in[9];
    float* out = (float*)d_out;

    init_deg_kernel<<<(NN + 255) / 256, 256>>>();
    count_kernel<<<(EE + 255) / 256, 256>>>(ei + EE);
    partials_kernel<<<NBLK, 256>>>();
    scan_chunks_kernel<<<NBLK, 256>>>();
    bin_kernel<<<(EE + NN + 255) / 256, 256>>>(ei);

    const int GEMM_BLOCKS = (NN + 63) / 64;
    const int SPMM_BLOCKS = (NN * 32 + 255) / 256;

    gemm_kernel<37><<<GEMM_BLOCKS, 128>>>(x, W1, 0);
    spmm_epi_kernel<<<SPMM_BLOCKS, 256>>>(0, b,       gma,       bta,       mu,       var,       out);
    gemm_kernel<64><<<GEMM_BLOCKS, 128>>>(nullptr, W2, 1);
    spmm_epi_kernel<<<SPMM_BLOCKS, 256>>>(1, b + 64,  gma + 64,  bta + 64,  mu + 64,  var + 64,  out);
    gemm_kernel<64><<<GEMM_BLOCKS, 128>>>(nullptr, W3, 2);
    spmm_epi_kernel<<<SPMM_BLOCKS, 256>>>(2, b + 128, gma + 128, bta + 128, mu + 128, var + 128, out);
}

// round 4
// speedup vs baseline: 1.1199x; 1.1199x over previous
#include <cuda_runtime.h>
#include <cuda_bf16.h>
#include <cuda_fp16.h>

#define NN 100000
#define EE 1000000
#define HID 64
#define NCHUNK 1024
#define NBLK 98            // ceil(NN / NCHUNK)
#define BN_EPS 1e-5f

// ---------------- scratch ----------------------------------------------------
__device__ __align__(16)  int    g_deg[NN];
__device__ __align__(16)  float  g_dinv[NN];
__device__ __align__(16)  int    g_rowptr[NN + 1];
__device__ __align__(16)  int    g_cursor[NN];
__device__ __align__(16)  int    g_src[EE + NN];
__device__ __align__(128) __half g_h[NN * HID];     // fp16 features for the gather
__device__ __align__(16)  float  g_x1[NN * HID];
__device__ __align__(16)  float  g_x2[NN * HID];
__device__ __align__(16)  int    g_bsum[128];

// ---------------- preprocessing ---------------------------------------------

__global__ void init_deg_kernel() {
    int i = blockIdx.x * blockDim.x + threadIdx.x;
    if (i < NN) g_deg[i] = 1;          // self loop
    if (i == 0) g_rowptr[NN] = EE + NN;
}

// edge_index is int32; ei[0..EE)=src, ei[EE..2EE)=dst
__global__ void count_kernel(const int* __restrict__ col) {
    int i = blockIdx.x * blockDim.x + threadIdx.x;
    if (i < EE) {
        unsigned c = (unsigned)col[i];
        if (c < NN) atomicAdd(&g_deg[c], 1);
    }
}

// per-1024-chunk degree sums + dinv
__global__ void partials_kernel() {
    int tid = threadIdx.x, b = blockIdx.x;
    int base = b * NCHUNK + tid * 4;
    int s = 0;
#pragma unroll
    for (int j = 0; j < 4; j++) {
        int idx = base + j;
        if (idx < NN) {
            int d = g_deg[idx];
            s += d;
            g_dinv[idx] = rsqrtf((float)d);
        }
    }
    for (int d = 16; d; d >>= 1) s += __shfl_down_sync(0xffffffffu, s, d);
    __shared__ int wsum[8];
    int lane = tid & 31, wid = tid >> 5;
    if (lane == 0) wsum[wid] = s;
    __syncthreads();
    if (tid == 0) {
        int t = 0;
#pragma unroll
        for (int i = 0; i < 8; i++) t += wsum[i];
        g_bsum[b] = t;
    }
}

// fused: each block derives its chunk offset from g_bsum, then scans its chunk
__global__ void scan_chunks_kernel() {
    int b = blockIdx.x, tid = threadIdx.x;
    int lane = tid & 31, wid = tid >> 5;

    int p = (tid < b && tid < NBLK) ? g_bsum[tid] : 0;   // blockDim 256 >= NBLK
    for (int d = 16; d; d >>= 1) p += __shfl_down_sync(0xffffffffu, p, d);
    __shared__ int psum[8];
    if (lane == 0) psum[wid] = p;
    __syncthreads();
    __shared__ int chunk_off;
    if (tid == 0) {
        int t = 0;
#pragma unroll
        for (int i = 0; i < 8; i++) t += psum[i];
        chunk_off = t;
    }

    int base = b * NCHUNK + tid * 4;
    int v[4]; int s = 0;
#pragma unroll
    for (int j = 0; j < 4; j++) {
        int idx = base + j;
        v[j] = (idx < NN) ? g_deg[idx] : 0;
        s += v[j];
    }
    int x = s;
#pragma unroll
    for (int d = 1; d < 32; d <<= 1) {
        int y = __shfl_up_sync(0xffffffffu, x, d);
        if (lane >= d) x += y;
    }
    __shared__ int wsum[8], woff[8];
    if (lane == 31) wsum[wid] = x;
    __syncthreads();
    if (tid == 0) {
        int run = 0;
#pragma unroll
        for (int i = 0; i < 8; i++) { int t = wsum[i]; woff[i] = run; run += t; }
    }
    __syncthreads();
    int pos = chunk_off + woff[wid] + (x - s);
#pragma unroll
    for (int j = 0; j < 4; j++) {
        int idx = base + j;
        if (idx < NN) {
            g_rowptr[idx] = pos;
            g_cursor[idx] = pos;
            pos += v[j];
        }
    }
}

__global__ void bin_kernel(const int* __restrict__ ei) {
    int i = blockIdx.x * blockDim.x + threadIdx.x;
    if (i >= EE + NN) return;
    unsigned s, c;
    if (i < EE) { s = (unsigned)ei[i]; c = (unsigned)ei[EE + i]; }
    else        { s = c = (unsigned)(i - EE); }
    if (s >= NN || c >= NN) return;
    int p = atomicAdd(&g_cursor[c], 1);
    if ((unsigned)p < (unsigned)(EE + NN)) g_src[p] = (int)s;
}

// ---------------- GEMM: h[n,:] = fp16( dinv[n] * (X[n,:] @ W) ) --------------
// 64 nodes / block, 256 threads, 4x4 register tile per thread (R2 shape).
template <int K>
__global__ void gemm_kernel(const float* __restrict__ Xext,
                            const float* __restrict__ W, int layer) {
    __shared__ __align__(16) float xs[64 * K];
    __shared__ __align__(16) float ws[K * HID];
    const float* X = Xext ? Xext : (layer == 1 ? (const float*)g_x1 : (const float*)g_x2);

    const int tid  = threadIdx.x;
    const int base = blockIdx.x * 64;

    for (int i = tid; i < K * HID; i += 256) ws[i] = W[i];
    for (int i = tid; i < 64 * K; i += 256) {
        int n = base + i / K;
        xs[i] = (n < NN) ? X[(size_t)base * K + i] : 0.0f;
    }
    __syncthreads();

    const int cgrp = tid & 15;   // 16 col groups x 4 cols
    const int ngrp = tid >> 4;   // 16 node groups x 4 nodes
    float acc[4][4];
#pragma unroll
    for (int j = 0; j < 4; j++)
#pragma unroll
        for (int q = 0; q < 4; q++) acc[j][q] = 0.0f;

#pragma unroll 4
    for (int k = 0; k < K; k++) {
        float4 w4 = *(const float4*)&ws[k * HID + cgrp * 4];
#pragma unroll
        for (int j = 0; j < 4; j++) {
            float xv = xs[(ngrp * 4 + j) * K + k];
            acc[j][0] += xv * w4.x;
            acc[j][1] += xv * w4.y;
            acc[j][2] += xv * w4.z;
            acc[j][3] += xv * w4.w;
        }
    }

#pragma unroll
    for (int j = 0; j < 4; j++) {
        int n = base + ngrp * 4 + j;
        if (n < NN) {
            float di = g_dinv[n];
            __half2 h0 = __floats2half2_rn(di * acc[j][0], di * acc[j][1]);
            __half2 h1 = __floats2half2_rn(di * acc[j][2], di * acc[j][3]);
            *(__half2*)&g_h[n * HID + cgrp * 4]     = h0;
            *(__half2*)&g_h[n * HID + cgrp * 4 + 2] = h1;
        }
    }
}

// ---------------- SpMM (gather fp16, CSR) + fused BN/ReLU/residual -----------
// one warp per node, 2 cols per lane (half2 -> 4B/lane, 128B/warp/edge), unroll-4
__global__ void spmm_epi_kernel(int layer,
                                const float* __restrict__ bias,
                                const float* __restrict__ gamma,
                                const float* __restrict__ beta,
                                const float* __restrict__ mean,
                                const float* __restrict__ var,
                                float* __restrict__ out_final) {
    int gw = (blockIdx.x * blockDim.x + threadIdx.x) >> 5;
    if (gw >= NN) return;
    int lane = threadIdx.x & 31;
    int c = lane * 2;

    const __half* __restrict__ H = g_h;
    const float* resid = (layer == 0) ? nullptr
                        : (layer == 1 ? (const float*)g_x1 : (const float*)g_x2);
    float* out = (layer == 0) ? g_x1 : (layer == 1 ? g_x2 : out_final);

    int beg = g_rowptr[gw];
    int end = g_rowptr[gw + 1];

    float2 a0 = make_float2(0.f, 0.f), a1 = make_float2(0.f, 0.f);
    float2 a2 = make_float2(0.f, 0.f), a3 = make_float2(0.f, 0.f);
    int e = beg;
    for (; e + 3 < end; e += 4) {
        int s0 = g_src[e],     s1 = g_src[e + 1];
        int s2 = g_src[e + 2], s3 = g_src[e + 3];
        float2 v0 = __half22float2(*(const __half2*)(H + s0 * HID + c));
        float2 v1 = __half22float2(*(const __half2*)(H + s1 * HID + c));
        float2 v2 = __half22float2(*(const __half2*)(H + s2 * HID + c));
        float2 v3 = __half22float2(*(const __half2*)(H + s3 * HID + c));
        a0.x += v0.x; a0.y += v0.y;
        a1.x += v1.x; a1.y += v1.y;
        a2.x += v2.x; a2.y += v2.y;
        a3.x += v3.x; a3.y += v3.y;
    }
    for (; e < end; e++) {
        int s = g_src[e];
        float2 v = __half22float2(*(const __half2*)(H + s * HID + c));
        a0.x += v.x; a0.y += v.y;
    }

    float sx = (a0.x + a1.x) + (a2.x + a3.x);
    float sy = (a0.y + a1.y) + (a2.y + a3.y);

    float di = g_dinv[gw];
    float scx = gamma[c]     * rsqrtf(var[c]     + BN_EPS);
    float scy = gamma[c + 1] * rsqrtf(var[c + 1] + BN_EPS);
    float vx = (sx * di + bias[c]     - mean[c])     * scx + beta[c];
    float vy = (sy * di + bias[c + 1] - mean[c + 1]) * scy + beta[c + 1];
    vx = fmaxf(vx, 0.0f);
    vy = fmaxf(vy, 0.0f);
    if (resid) {
        float2 r = *(const float2*)(resid + gw * HID + c);
        vx += r.x; vy += r.y;
    }
    *(float2*)(out + gw * HID + c) = make_float2(vx, vy);
}

// ---------------- launch -----------------------------------------------------
extern "C" void kernel_launch(void* const* d_in, const int* in_sizes, int n_in,
                              void* d_out, int out_size) {
    const float* x   = (const float*)d_in[0];
    const int*   ei  = (const int*)d_in[1];     // int32 (JAX default, no x64)
    const float* W1  = (const float*)d_in[2];
    const float* W2  = (const float*)d_in[3];
    const float* W3  = (const float*)d_in[4];
    const float* b   = (const float*)d_in[5];
    const float* gma = (const float*)d_in[6];
    const float* bta = (const float*)d_in[7];
    const float* mu  = (const float*)d_in[8];
    const float* var = (const float*)d_in[9];
    float* out = (float*)d_out;

    init_deg_kernel<<<(NN + 255) / 256, 256>>>();
    count_kernel<<<(EE + 255) / 256, 256>>>(ei + EE);
    partials_kernel<<<NBLK, 256>>>();
    scan_chunks_kernel<<<NBLK, 256>>>();
    bin_kernel<<<(EE + NN + 255) / 256, 256>>>(ei);

    const int GEMM_BLOCKS = (NN + 63) / 64;
    const int SPMM_BLOCKS = (NN * 32 + 255) / 256;

    gemm_kernel<37><<<GEMM_BLOCKS, 256>>>(x, W1, 0);
    spmm_epi_kernel<<<SPMM_BLOCKS, 256>>>(0, b,       gma,       bta,       mu,       var,       out);
    gemm_kernel<64><<<GEMM_BLOCKS, 256>>>(nullptr, W2, 1);
    spmm_epi_kernel<<<SPMM_BLOCKS, 256>>>(1, b + 64,  gma + 64,  bta + 64,  mu + 64,  var + 64,  out);
    gemm_kernel<64><<<GEMM_BLOCKS, 256>>>(nullptr, W3, 2);
    spmm_epi_kernel<<<SPMM_BLOCKS, 256>>>(2, b + 128, gma + 128, bta + 128, mu + 128, var + 128, out);
}

// round 5
// speedup vs baseline: 1.2950x; 1.1564x over previous
#include <cuda_runtime.h>
#include <cuda_bf16.h>
#include <cuda_fp16.h>

#define NN 100000
#define EE 1000000
#define HID 64
#define NCHUNK 1024
#define NBLK 98            // ceil(NN / NCHUNK)
#define BN_EPS 1e-5f
#define XS_STRIDE 72       // 64 + 8-half pad -> conflict-free fragment LDS

// ---------------- scratch ----------------------------------------------------
__device__ __align__(16)  int    g_deg[NN];
__device__ __align__(16)  float  g_dinv[NN];
__device__ __align__(16)  int    g_rowptr[NN + 1];
__device__ __align__(16)  int    g_cursor[NN];
__device__ __align__(16)  int    g_src[EE + NN];
__device__ __align__(128) __half g_h[NN * HID];      // fp16 features for the gather
__device__ __align__(16)  float  g_x1[NN * HID];
__device__ __align__(16)  float  g_x2[NN * HID];
__device__ __align__(16)  int    g_bsum[128];
__device__ __align__(16)  __half g_wt[3][HID * HID]; // transposed fp16 weights [n][k], zero-padded

// ---------------- preprocessing ---------------------------------------------

__global__ void init_deg_kernel() {
    int i = blockIdx.x * blockDim.x + threadIdx.x;
    if (i < NN) g_deg[i] = 1;          // self loop
    if (i == 0) g_rowptr[NN] = EE + NN;
}

__global__ void count_kernel(const int* __restrict__ col) {
    int i = blockIdx.x * blockDim.x + threadIdx.x;
    if (i < EE) {
        unsigned c = (unsigned)col[i];
        if (c < NN) atomicAdd(&g_deg[c], 1);
    }
}

__global__ void partials_kernel() {
    int tid = threadIdx.x, b = blockIdx.x;
    int base = b * NCHUNK + tid * 4;
    int s = 0;
#pragma unroll
    for (int j = 0; j < 4; j++) {
        int idx = base + j;
        if (idx < NN) {
            int d = g_deg[idx];
            s += d;
            g_dinv[idx] = rsqrtf((float)d);
        }
    }
    for (int d = 16; d; d >>= 1) s += __shfl_down_sync(0xffffffffu, s, d);
    __shared__ int wsum[8];
    int lane = tid & 31, wid = tid >> 5;
    if (lane == 0) wsum[wid] = s;
    __syncthreads();
    if (tid == 0) {
        int t = 0;
#pragma unroll
        for (int i = 0; i < 8; i++) t += wsum[i];
        g_bsum[b] = t;
    }
}

// fused: each block derives its chunk offset from g_bsum, then scans its chunk
__global__ void scan_chunks_kernel() {
    int b = blockIdx.x, tid = threadIdx.x;
    int lane = tid & 31, wid = tid >> 5;

    int p = (tid < b && tid < NBLK) ? g_bsum[tid] : 0;
    for (int d = 16; d; d >>= 1) p += __shfl_down_sync(0xffffffffu, p, d);
    __shared__ int psum[8];
    if (lane == 0) psum[wid] = p;
    __syncthreads();
    __shared__ int chunk_off;
    if (tid == 0) {
        int t = 0;
#pragma unroll
        for (int i = 0; i < 8; i++) t += psum[i];
        chunk_off = t;
    }

    int base = b * NCHUNK + tid * 4;
    int v[4]; int s = 0;
#pragma unroll
    for (int j = 0; j < 4; j++) {
        int idx = base + j;
        v[j] = (idx < NN) ? g_deg[idx] : 0;
        s += v[j];
    }
    int x = s;
#pragma unroll
    for (int d = 1; d < 32; d <<= 1) {
        int y = __shfl_up_sync(0xffffffffu, x, d);
        if (lane >= d) x += y;
    }
    __shared__ int wsum[8], woff[8];
    if (lane == 31) wsum[wid] = x;
    __syncthreads();
    if (tid == 0) {
        int run = 0;
#pragma unroll
        for (int i = 0; i < 8; i++) { int t = wsum[i]; woff[i] = run; run += t; }
    }
    __syncthreads();
    int pos = chunk_off + woff[wid] + (x - s);
#pragma unroll
    for (int j = 0; j < 4; j++) {
        int idx = base + j;
        if (idx < NN) {
            g_rowptr[idx] = pos;
            g_cursor[idx] = pos;
            pos += v[j];
        }
    }
}

__global__ void bin_kernel(const int* __restrict__ ei) {
    int i = blockIdx.x * blockDim.x + threadIdx.x;
    if (i >= EE + NN) return;
    unsigned s, c;
    if (i < EE) { s = (unsigned)ei[i]; c = (unsigned)ei[EE + i]; }
    else        { s = c = (unsigned)(i - EE); }
    if (s >= NN || c >= NN) return;
    int p = atomicAdd(&g_cursor[c], 1);
    if ((unsigned)p < (unsigned)(EE + NN)) g_src[p] = (int)s;
}

// ---------------- weight prep: g_wt[l][n][k] = fp16(W_l[k][n]), zero-padded --
__global__ void wconv_kernel(const float* __restrict__ W1,
                             const float* __restrict__ W2,
                             const float* __restrict__ W3) {
    int i = blockIdx.x * blockDim.x + threadIdx.x;
    if (i >= 3 * HID * HID) return;
    int l = i / (HID * HID);
    int rem = i - l * (HID * HID);
    int n = rem >> 6, k = rem & 63;
    const float* W = (l == 0) ? W1 : (l == 1 ? W2 : W3);
    int K = (l == 0) ? 37 : 64;
    float v = (k < K) ? W[k * HID + n] : 0.0f;
    g_wt[l][n * HID + k] = __float2half_rn(v);
}

// ---------------- GEMM via mma.sync m16n8k16: h = fp16(dinv * (X @ W)) -------
// 64 nodes / block, 128 threads (4 warps, 16 rows each), K padded to 64.
// KIN: 37 (layer 0, Xext) / 64 (layers 1,2 from g_x1/g_x2 selected by layer)
template <int KIN>
__global__ void __launch_bounds__(128) gemm_mma_kernel(const float* __restrict__ Xext,
                                                       int layer) {
    __shared__ __align__(16) __half Xs[64 * XS_STRIDE];
    __shared__ __align__(16) __half Wts[64 * XS_STRIDE];

    const float* X = (KIN == 37) ? Xext
                     : (layer == 1 ? (const float*)g_x1 : (const float*)g_x2);
    const __half* Wt = g_wt[layer];

    const int tid  = threadIdx.x;
    const int base = blockIdx.x * 64;

    // stage Wt [64][64] -> smem with pad stride
    for (int i = tid; i < 64 * 32; i += 128) {
        int n = i >> 5, k2 = (i & 31) * 2;
        *(__half2*)&Wts[n * XS_STRIDE + k2] = *(const __half2*)&Wt[n * HID + k2];
    }

    // stage X -> fp16 smem (zero-padded cols KIN..63, zero rows past NN)
    if constexpr (KIN == 64) {
        for (int i = tid; i < 64 * 16; i += 128) {
            int n = i >> 4, c4 = (i & 15) * 4;
            float4 v = make_float4(0.f, 0.f, 0.f, 0.f);
            if (base + n < NN) v = *(const float4*)&X[(size_t)(base + n) * 64 + c4];
            *(__half2*)&Xs[n * XS_STRIDE + c4]     = __floats2half2_rn(v.x, v.y);
            *(__half2*)&Xs[n * XS_STRIDE + c4 + 2] = __floats2half2_rn(v.z, v.w);
        }
    } else {
        for (int i = tid; i < 64 * 64; i += 128) {
            int n = i >> 6, k = i & 63;
            float v = (k < KIN && base + n < NN) ? X[(size_t)(base + n) * KIN + k] : 0.0f;
            Xs[n * XS_STRIDE + k] = __float2half_rn(v);
        }
    }
    __syncthreads();

    const int w    = tid >> 5;       // warp: rows 16w..16w+15
    const int lane = tid & 31;
    const int g    = lane >> 2;      // groupID
    const int t    = lane & 3;       // threadID_in_group

    float acc[8][4];
#pragma unroll
    for (int nt = 0; nt < 8; nt++)
#pragma unroll
        for (int q = 0; q < 4; q++) acc[nt][q] = 0.0f;

    const int rowA0 = (16 * w + g)     * XS_STRIDE;
    const int rowA1 = (16 * w + g + 8) * XS_STRIDE;

#pragma unroll
    for (int kt = 0; kt < 4; kt++) {
        const int kb = kt * 16 + 2 * t;
        unsigned a0 = *(const unsigned*)&Xs[rowA0 + kb];
        unsigned a1 = *(const unsigned*)&Xs[rowA1 + kb];
        unsigned a2 = *(const unsigned*)&Xs[rowA0 + kb + 8];
        unsigned a3 = *(const unsigned*)&Xs[rowA1 + kb + 8];
#pragma unroll
        for (int nt = 0; nt < 8; nt++) {
            unsigned b0 = *(const unsigned*)&Wts[(8 * nt + g) * XS_STRIDE + kb];
            unsigned b1 = *(const unsigned*)&Wts[(8 * nt + g) * XS_STRIDE + kb + 8];
            asm volatile(
                "mma.sync.aligned.m16n8k16.row.col.f32.f16.f16.f32 "
                "{%0,%1,%2,%3}, {%4,%5,%6,%7}, {%8,%9}, {%0,%1,%2,%3};"
                : "+f"(acc[nt][0]), "+f"(acc[nt][1]), "+f"(acc[nt][2]), "+f"(acc[nt][3])
                : "r"(a0), "r"(a1), "r"(a2), "r"(a3), "r"(b0), "r"(b1));
        }
    }

    // epilogue: scale by dinv[row], write fp16 h
    int r0 = base + 16 * w + g;
    int r1 = r0 + 8;
    float d0 = (r0 < NN) ? g_dinv[r0] : 0.0f;
    float d1 = (r1 < NN) ? g_dinv[r1] : 0.0f;
#pragma unroll
    for (int nt = 0; nt < 8; nt++) {
        int col = 8 * nt + 2 * t;
        if (r0 < NN)
            *(__half2*)&g_h[r0 * HID + col] = __floats2half2_rn(d0 * acc[nt][0], d0 * acc[nt][1]);
        if (r1 < NN)
            *(__half2*)&g_h[r1 * HID + col] = __floats2half2_rn(d1 * acc[nt][2], d1 * acc[nt][3]);
    }
}

// ---------------- SpMM (gather fp16, CSR) + fused BN/ReLU/residual -----------
// one warp per 4 nodes, 2 cols per lane, params hoisted per warp
__global__ void spmm_epi_kernel(int layer,
                                const float* __restrict__ bias,
                                const float* __restrict__ gamma,
                                const float* __restrict__ beta,
                                const float* __restrict__ mean,
                                const float* __restrict__ var,
                                float* __restrict__ out_final) {
    int w = (blockIdx.x * blockDim.x + threadIdx.x) >> 5;
    int n0 = w * 4;
    if (n0 >= NN) return;
    int lane = threadIdx.x & 31;
    int c = lane * 2;

    const __half* __restrict__ H = g_h;
    const float* resid = (layer == 0) ? nullptr
                        : (layer == 1 ? (const float*)g_x1 : (const float*)g_x2);
    float* out = (layer == 0) ? g_x1 : (layer == 1 ? g_x2 : out_final);

    float bx = bias[c],  by = bias[c + 1];
    float mx = mean[c],  my = mean[c + 1];
    float btx = beta[c], bty = beta[c + 1];
    float scx = gamma[c]     * rsqrtf(var[c]     + BN_EPS);
    float scy = gamma[c + 1] * rsqrtf(var[c + 1] + BN_EPS);

#pragma unroll
    for (int j = 0; j < 4; j++) {
        int node = n0 + j;
        if (node >= NN) break;
        int beg = g_rowptr[node];
        int end = g_rowptr[node + 1];

        float2 a0 = make_float2(0.f, 0.f), a1 = make_float2(0.f, 0.f);
        float2 a2 = make_float2(0.f, 0.f), a3 = make_float2(0.f, 0.f);
        int e = beg;
        for (; e + 3 < end; e += 4) {
            int s0 = g_src[e],     s1 = g_src[e + 1];
            int s2 = g_src[e + 2], s3 = g_src[e + 3];
            float2 v0 = __half22float2(*(const __half2*)(H + s0 * HID + c));
            float2 v1 = __half22float2(*(const __half2*)(H + s1 * HID + c));
            float2 v2 = __half22float2(*(const __half2*)(H + s2 * HID + c));
            float2 v3 = __half22float2(*(const __half2*)(H + s3 * HID + c));
            a0.x += v0.x; a0.y += v0.y;
            a1.x += v1.x; a1.y += v1.y;
            a2.x += v2.x; a2.y += v2.y;
            a3.x += v3.x; a3.y += v3.y;
        }
        for (; e < end; e++) {
            int s = g_src[e];
            float2 v = __half22float2(*(const __half2*)(H + s * HID + c));
            a0.x += v.x; a0.y += v.y;
        }

        float sx = (a0.x + a1.x) + (a2.x + a3.x);
        float sy = (a0.y + a1.y) + (a2.y + a3.y);

        float di = g_dinv[node];
        float vx = (sx * di + bx - mx) * scx + btx;
        float vy = (sy * di + by - my) * scy + bty;
        vx = fmaxf(vx, 0.0f);
        vy = fmaxf(vy, 0.0f);
        if (resid) {
            float2 r = *(const float2*)(resid + node * HID + c);
            vx += r.x; vy += r.y;
        }
        *(float2*)(out + node * HID + c) = make_float2(vx, vy);
    }
}

// ---------------- launch -----------------------------------------------------
extern "C" void kernel_launch(void* const* d_in, const int* in_sizes, int n_in,
                              void* d_out, int out_size) {
    const float* x   = (const float*)d_in[0];
    const int*   ei  = (const int*)d_in[1];     // int32 (JAX default, no x64)
    const float* W1  = (const float*)d_in[2];
    const float* W2  = (const float*)d_in[3];
    const float* W3  = (const float*)d_in[4];
    const float* b   = (const float*)d_in[5];
    const float* gma = (const float*)d_in[6];
    const float* bta = (const float*)d_in[7];
    const float* mu  = (const float*)d_in[8];
    const float* var = (const float*)d_in[9];
    float* out = (float*)d_out;

    wconv_kernel<<<(3 * HID * HID + 255) / 256, 256>>>(W1, W2, W3);
    init_deg_kernel<<<(NN + 255) / 256, 256>>>();
    count_kernel<<<(EE + 255) / 256, 256>>>(ei + EE);
    partials_kernel<<<NBLK, 256>>>();
    scan_chunks_kernel<<<NBLK, 256>>>();
    bin_kernel<<<(EE + NN + 255) / 256, 256>>>(ei);

    const int GEMM_BLOCKS = (NN + 63) / 64;
    const int SPMM_BLOCKS = ((NN + 3) / 4 * 32 + 255) / 256;

    gemm_mma_kernel<37><<<GEMM_BLOCKS, 128>>>(x, 0);
    spmm_epi_kernel<<<SPMM_BLOCKS, 256>>>(0, b,       gma,       bta,       mu,       var,       out);
    gemm_mma_kernel<64><<<GEMM_BLOCKS, 128>>>(nullptr, 1);
    spmm_epi_kernel<<<SPMM_BLOCKS, 256>>>(1, b + 64,  gma + 64,  bta + 64,  mu + 64,  var + 64,  out);
    gemm_mma_kernel<64><<<GEMM_BLOCKS, 128>>>(nullptr, 2);
    spmm_epi_kernel<<<SPMM_BLOCKS, 256>>>(2, b + 128, gma + 128, bta + 128, mu + 128, var + 128, out);
}

// round 6
// speedup vs baseline: 1.3483x; 1.0412x over previous
#include <cuda_runtime.h>
#include <cuda_bf16.h>
#include <cuda_fp16.h>

#define NN 100000
#define EE 1000000
#define HID 64
#define NCHUNK 1024
#define NBLK 98            // ceil(NN / NCHUNK)
#define BN_EPS 1e-5f
#define XS_STRIDE 72       // 64 + 8-half pad -> conflict-free fragment LDS

// ---------------- scratch ----------------------------------------------------
__device__ __align__(16)  int    g_deg[NN];
__device__ __align__(16)  float  g_dinv[NN];
__device__ __align__(16)  int    g_rowptr[NN + 1];
__device__ __align__(16)  int    g_cursor[NN];
__device__ __align__(16)  int    g_src[EE + NN];
__device__ __align__(128) __half g_h[NN * HID];      // fp16 features for the gather
__device__ __align__(16)  float  g_x1[NN * HID];
__device__ __align__(16)  float  g_x2[NN * HID];
__device__ __align__(16)  int    g_bsum[128];
__device__ __align__(16)  __half g_wt[3][HID * HID]; // transposed fp16 weights [n][k], zero-padded

// ---------------- preprocessing ---------------------------------------------

// init degrees (self loop) + convert weights (first 12288 threads) in one launch
__global__ void init_kernel(const float* __restrict__ W1,
                            const float* __restrict__ W2,
                            const float* __restrict__ W3) {
    int i = blockIdx.x * blockDim.x + threadIdx.x;
    if (i < NN) g_deg[i] = 1;
    if (i == 0) g_rowptr[NN] = EE + NN;
    if (i < 3 * HID * HID) {
        int l = i / (HID * HID);
        int rem = i - l * (HID * HID);
        int n = rem >> 6, k = rem & 63;
        const float* W = (l == 0) ? W1 : (l == 1 ? W2 : W3);
        int K = (l == 0) ? 37 : 64;
        float v = (k < K) ? W[k * HID + n] : 0.0f;
        g_wt[l][n * HID + k] = __float2half_rn(v);
    }
}

// vectorized: 4 destination indices per thread
__global__ void count_kernel(const int4* __restrict__ col4) {
    int i = blockIdx.x * blockDim.x + threadIdx.x;
    if (i < EE / 4) {
        int4 c = col4[i];
        if ((unsigned)c.x < NN) atomicAdd(&g_deg[c.x], 1);
        if ((unsigned)c.y < NN) atomicAdd(&g_deg[c.y], 1);
        if ((unsigned)c.z < NN) atomicAdd(&g_deg[c.z], 1);
        if ((unsigned)c.w < NN) atomicAdd(&g_deg[c.w], 1);
    }
}

__global__ void partials_kernel() {
    int tid = threadIdx.x, b = blockIdx.x;
    int base = b * NCHUNK + tid * 4;
    int s = 0;
#pragma unroll
    for (int j = 0; j < 4; j++) {
        int idx = base + j;
        if (idx < NN) {
            int d = g_deg[idx];
            s += d;
            g_dinv[idx] = rsqrtf((float)d);
        }
    }
    for (int d = 16; d; d >>= 1) s += __shfl_down_sync(0xffffffffu, s, d);
    __shared__ int wsum[8];
    int lane = tid & 31, wid = tid >> 5;
    if (lane == 0) wsum[wid] = s;
    __syncthreads();
    if (tid == 0) {
        int t = 0;
#pragma unroll
        for (int i = 0; i < 8; i++) t += wsum[i];
        g_bsum[b] = t;
    }
}

// fused: each block derives its chunk offset from g_bsum, then scans its chunk
__global__ void scan_chunks_kernel() {
    int b = blockIdx.x, tid = threadIdx.x;
    int lane = tid & 31, wid = tid >> 5;

    int p = (tid < b && tid < NBLK) ? g_bsum[tid] : 0;
    for (int d = 16; d; d >>= 1) p += __shfl_down_sync(0xffffffffu, p, d);
    __shared__ int psum[8];
    if (lane == 0) psum[wid] = p;
    __syncthreads();
    __shared__ int chunk_off;
    if (tid == 0) {
        int t = 0;
#pragma unroll
        for (int i = 0; i < 8; i++) t += psum[i];
        chunk_off = t;
    }

    int base = b * NCHUNK + tid * 4;
    int v[4]; int s = 0;
#pragma unroll
    for (int j = 0; j < 4; j++) {
        int idx = base + j;
        v[j] = (idx < NN) ? g_deg[idx] : 0;
        s += v[j];
    }
    int x = s;
#pragma unroll
    for (int d = 1; d < 32; d <<= 1) {
        int y = __shfl_up_sync(0xffffffffu, x, d);
        if (lane >= d) x += y;
    }
    __shared__ int wsum[8], woff[8];
    if (lane == 31) wsum[wid] = x;
    __syncthreads();
    if (tid == 0) {
        int run = 0;
#pragma unroll
        for (int i = 0; i < 8; i++) { int t = wsum[i]; woff[i] = run; run += t; }
    }
    __syncthreads();
    int pos = chunk_off + woff[wid] + (x - s);
#pragma unroll
    for (int j = 0; j < 4; j++) {
        int idx = base + j;
        if (idx < NN) {
            g_rowptr[idx] = pos;
            g_cursor[idx] = pos;
            pos += v[j];
        }
    }
}

__global__ void bin_kernel(const int* __restrict__ ei) {
    int i = blockIdx.x * blockDim.x + threadIdx.x;
    if (i >= EE + NN) return;
    unsigned s, c;
    if (i < EE) { s = (unsigned)ei[i]; c = (unsigned)ei[EE + i]; }
    else        { s = c = (unsigned)(i - EE); }
    if (s >= NN || c >= NN) return;
    int p = atomicAdd(&g_cursor[c], 1);
    if ((unsigned)p < (unsigned)(EE + NN)) g_src[p] = (int)s;
}

// ---------------- GEMM via mma.sync m16n8k16: h = fp16(dinv * (X @ W)) -------
// 64 nodes / block, 128 threads (4 warps, 16 rows each), K padded to 64.
template <int KIN>
__global__ void __launch_bounds__(128) gemm_mma_kernel(const float* __restrict__ Xext,
                                                       int layer) {
    __shared__ __align__(16) __half Xs[64 * XS_STRIDE];
    __shared__ __align__(16) __half Wts[64 * XS_STRIDE];

    const float* X = (KIN == 37) ? Xext
                     : (layer == 1 ? (const float*)g_x1 : (const float*)g_x2);
    const __half* Wt = g_wt[layer];

    const int tid  = threadIdx.x;
    const int base = blockIdx.x * 64;

    for (int i = tid; i < 64 * 32; i += 128) {
        int n = i >> 5, k2 = (i & 31) * 2;
        *(__half2*)&Wts[n * XS_STRIDE + k2] = *(const __half2*)&Wt[n * HID + k2];
    }

    if constexpr (KIN == 64) {
        for (int i = tid; i < 64 * 16; i += 128) {
            int n = i >> 4, c4 = (i & 15) * 4;
            float4 v = make_float4(0.f, 0.f, 0.f, 0.f);
            if (base + n < NN) v = *(const float4*)&X[(size_t)(base + n) * 64 + c4];
            *(__half2*)&Xs[n * XS_STRIDE + c4]     = __floats2half2_rn(v.x, v.y);
            *(__half2*)&Xs[n * XS_STRIDE + c4 + 2] = __floats2half2_rn(v.z, v.w);
        }
    } else {
        for (int i = tid; i < 64 * 64; i += 128) {
            int n = i >> 6, k = i & 63;
            float v = (k < KIN && base + n < NN) ? X[(size_t)(base + n) * KIN + k] : 0.0f;
            Xs[n * XS_STRIDE + k] = __float2half_rn(v);
        }
    }
    __syncthreads();

    const int w    = tid >> 5;
    const int lane = tid & 31;
    const int g    = lane >> 2;
    const int t    = lane & 3;

    float acc[8][4];
#pragma unroll
    for (int nt = 0; nt < 8; nt++)
#pragma unroll
        for (int q = 0; q < 4; q++) acc[nt][q] = 0.0f;

    const int rowA0 = (16 * w + g)     * XS_STRIDE;
    const int rowA1 = (16 * w + g + 8) * XS_STRIDE;

#pragma unroll
    for (int kt = 0; kt < 4; kt++) {
        const int kb = kt * 16 + 2 * t;
        unsigned a0 = *(const unsigned*)&Xs[rowA0 + kb];
        unsigned a1 = *(const unsigned*)&Xs[rowA1 + kb];
        unsigned a2 = *(const unsigned*)&Xs[rowA0 + kb + 8];
        unsigned a3 = *(const unsigned*)&Xs[rowA1 + kb + 8];
#pragma unroll
        for (int nt = 0; nt < 8; nt++) {
            unsigned b0 = *(const unsigned*)&Wts[(8 * nt + g) * XS_STRIDE + kb];
            unsigned b1 = *(const unsigned*)&Wts[(8 * nt + g) * XS_STRIDE + kb + 8];
            asm volatile(
                "mma.sync.aligned.m16n8k16.row.col.f32.f16.f16.f32 "
                "{%0,%1,%2,%3}, {%4,%5,%6,%7}, {%8,%9}, {%0,%1,%2,%3};"
                : "+f"(acc[nt][0]), "+f"(acc[nt][1]), "+f"(acc[nt][2]), "+f"(acc[nt][3])
                : "r"(a0), "r"(a1), "r"(a2), "r"(a3), "r"(b0), "r"(b1));
        }
    }

    int r0 = base + 16 * w + g;
    int r1 = r0 + 8;
    float d0 = (r0 < NN) ? g_dinv[r0] : 0.0f;
    float d1 = (r1 < NN) ? g_dinv[r1] : 0.0f;
#pragma unroll
    for (int nt = 0; nt < 8; nt++) {
        int col = 8 * nt + 2 * t;
        if (r0 < NN)
            *(__half2*)&g_h[r0 * HID + col] = __floats2half2_rn(d0 * acc[nt][0], d0 * acc[nt][1]);
        if (r1 < NN)
            *(__half2*)&g_h[r1 * HID + col] = __floats2half2_rn(d1 * acc[nt][2], d1 * acc[nt][3]);
    }
}

// ---------------- SpMM (gather fp16, CSR) + fused BN/ReLU/residual -----------
// one warp per 4 nodes, 2 cols per lane, unroll-8 (MLP=8), params hoisted
__global__ void spmm_epi_kernel(int layer,
                                const float* __restrict__ bias,
                                const float* __restrict__ gamma,
                                const float* __restrict__ beta,
                                const float* __restrict__ mean,
                                const float* __restrict__ var,
                                float* __restrict__ out_final) {
    int w = (blockIdx.x * blockDim.x + threadIdx.x) >> 5;
    int n0 = w * 4;
    if (n0 >= NN) return;
    int lane = threadIdx.x & 31;
    int c = lane * 2;

    const __half* __restrict__ H = g_h;
    const float* resid = (layer == 0) ? nullptr
                        : (layer == 1 ? (const float*)g_x1 : (const float*)g_x2);
    float* out = (layer == 0) ? g_x1 : (layer == 1 ? g_x2 : out_final);

    float bx = bias[c],  by = bias[c + 1];
    float mx = mean[c],  my = mean[c + 1];
    float btx = beta[c], bty = beta[c + 1];
    float scx = gamma[c]     * rsqrtf(var[c]     + BN_EPS);
    float scy = gamma[c + 1] * rsqrtf(var[c + 1] + BN_EPS);

#pragma unroll
    for (int j = 0; j < 4; j++) {
        int node = n0 + j;
        if (node >= NN) break;
        int beg = g_rowptr[node];
        int end = g_rowptr[node + 1];

        float2 a[8];
#pragma unroll
        for (int q = 0; q < 8; q++) a[q] = make_float2(0.f, 0.f);

        int e = beg;
        for (; e + 7 < end; e += 8) {
            int   s[8];
            float2 v[8];
#pragma unroll
            for (int q = 0; q < 8; q++) s[q] = g_src[e + q];
#pragma unroll
            for (int q = 0; q < 8; q++)
                v[q] = __half22float2(*(const __half2*)(H + s[q] * HID + c));
#pragma unroll
            for (int q = 0; q < 8; q++) { a[q].x += v[q].x; a[q].y += v[q].y; }
        }
        for (; e < end; e++) {
            int s = g_src[e];
            float2 v = __half22float2(*(const __half2*)(H + s * HID + c));
            a[0].x += v.x; a[0].y += v.y;
        }

        float sx = ((a[0].x + a[1].x) + (a[2].x + a[3].x)) +
                   ((a[4].x + a[5].x) + (a[6].x + a[7].x));
        float sy = ((a[0].y + a[1].y) + (a[2].y + a[3].y)) +
                   ((a[4].y + a[5].y) + (a[6].y + a[7].y));

        float di = g_dinv[node];
        float vx = (sx * di + bx - mx) * scx + btx;
        float vy = (sy * di + by - my) * scy + bty;
        vx = fmaxf(vx, 0.0f);
        vy = fmaxf(vy, 0.0f);
        if (resid) {
            float2 r = *(const float2*)(resid + node * HID + c);
            vx += r.x; vy += r.y;
        }
        *(float2*)(out + node * HID + c) = make_float2(vx, vy);
    }
}

// ---------------- launch -----------------------------------------------------
extern "C" void kernel_launch(void* const* d_in, const int* in_sizes, int n_in,
                              void* d_out, int out_size) {
    const float* x   = (const float*)d_in[0];
    const int*   ei  = (const int*)d_in[1];     // int32 (JAX default, no x64)
    const float* W1  = (const float*)d_in[2];
    const float* W2  = (const float*)d_in[3];
    const float* W3  = (const float*)d_in[4];
    const float* b   = (const float*)d_in[5];
    const float* gma = (const float*)d_in[6];
    const float* bta = (const float*)d_in[7];
    const float* mu  = (const float*)d_in[8];
    const float* var = (const float*)d_in[9];
    float* out = (float*)d_out;

    init_kernel<<<(NN + 255) / 256, 256>>>(W1, W2, W3);
    count_kernel<<<(EE / 4 + 255) / 256, 256>>>((const int4*)(ei + EE));
    partials_kernel<<<NBLK, 256>>>();
    scan_chunks_kernel<<<NBLK, 256>>>();
    bin_kernel<<<(EE + NN + 255) / 256, 256>>>(ei);

    const int GEMM_BLOCKS = (NN + 63) / 64;
    const int SPMM_BLOCKS = ((NN + 3) / 4 * 32 + 255) / 256;

    gemm_mma_kernel<37><<<GEMM_BLOCKS, 128>>>(x, 0);
    spmm_epi_kernel<<<SPMM_BLOCKS, 256>>>(0, b,       gma,       bta,       mu,       var,       out);
    gemm_mma_kernel<64><<<GEMM_BLOCKS, 128>>>(nullptr, 1);
    spmm_epi_kernel<<<SPMM_BLOCKS, 256>>>(1, b + 64,  gma + 64,  bta + 64,  mu + 64,  var + 64,  out);
    gemm_mma_kernel<64><<<GEMM_BLOCKS, 128>>>(nullptr, 2);
    spmm_epi_kernel<<<SPMM_BLOCKS, 256>>>(2, b + 128, gma + 128, bta + 128, mu + 128, var + 128, out);
}